// round 4
// baseline (speedup 1.0000x reference)
#include <cuda_runtime.h>
#include <math.h>

#define BB 256
#define TT 512
#define II 256
#define HH 512
#define AA 18
#define KK 768
#define NCTA 128
#define RT 64           // rows per CTA
#define JT 128          // cols per CTA
#define NSMAX 32
#define KSMAX 96

// ---------------- scratch ----------------
__device__ float g_W[(size_t)KK * HH];                         // [k][j]
__device__ float g_bias[HH];
__device__ float g_part[2][NSMAX][BB][HH];                     // 32 MB, parity-double-buffered
__device__ float g_hout[(size_t)BB * TT * HH];
__device__ int   g_perm[BB];
__device__ int   g_active[TT];
__device__ int   g_count;
__device__ int   g_gen;

// ---------------- cp.async ----------------
__device__ __forceinline__ void cpa16(void* sdst, const void* gsrc) {
    unsigned s = (unsigned)__cvta_generic_to_shared(sdst);
    asm volatile("cp.async.cg.shared.global [%0], [%1], 16;\n" :: "r"(s), "l"(gsrc));
}
#define CPA_COMMIT() asm volatile("cp.async.commit_group;\n" ::: "memory")
#define CPA_WAIT0()  asm volatile("cp.async.wait_group 0;\n" ::: "memory")

// ---------------- grid barrier (all 128 CTAs co-resident) ----------------
__device__ __forceinline__ void grid_sync(int target) {
    __syncthreads();
    if (threadIdx.x == 0) {
        __threadfence();
        int a = atomicAdd(&g_count, 1);
        if (a == NCTA * target - 1) {
            atomicExch(&g_gen, target);
        } else {
            while (*((volatile int*)&g_gen) < target) { }
            __threadfence();
        }
    }
    __syncthreads();
}

// ---------------- tiers ----------------
__device__ __forceinline__ void tier_of(int A, int& tier, int& rgsh, int& ns, int& ks) {
    if (A > 128)      { tier = 0; rgsh = 2; ns = 8;  ks = 96; }
    else if (A > 64)  { tier = 1; rgsh = 1; ns = 16; ks = 48; }
    else              { tier = 2; rgsh = 0; ns = 32; ks = 24; }
}

// ---------------- prep ----------------
__global__ void prep_sort(const int* __restrict__ lengths) {
    __shared__ int s_len[BB];
    __shared__ int s_hist[TT + 1];
    __shared__ int s_S[TT + 1];
    __shared__ int s_base[TT + 1];
    int tid = threadIdx.x;
    if (tid == 0) { g_count = 0; g_gen = 0; }
    if (tid < BB) s_len[tid] = lengths[tid];
    for (int i = tid; i <= TT; i += blockDim.x) s_hist[i] = 0;
    __syncthreads();
    if (tid < BB) atomicAdd(&s_hist[s_len[tid]], 1);
    __syncthreads();
    if (tid == 0) {
        s_S[TT] = 0;
        for (int v = TT - 1; v >= 0; --v) s_S[v] = s_S[v + 1] + s_hist[v + 1];
    }
    __syncthreads();
    for (int i = tid; i <= TT; i += blockDim.x) s_base[i] = s_S[i];
    if (tid < TT) g_active[tid] = s_S[tid];
    __syncthreads();
    if (tid < BB) {
        int pos = atomicAdd(&s_base[s_len[tid]], 1);
        g_perm[pos] = tid;
    }
}

__global__ void prep_pack(const float* __restrict__ W_ih, const float* __restrict__ W_hh,
                          const float* __restrict__ b_ih, const float* __restrict__ b_hh) {
    int idx = blockIdx.x * blockDim.x + threadIdx.x;
    int stride = gridDim.x * blockDim.x;
    for (int i = idx; i < KK * HH; i += stride) {
        int k = i / HH, j = i % HH;
        g_W[i] = (k < HH) ? W_hh[(size_t)j * HH + k] : W_ih[(size_t)j * II + (k - HH)];
    }
    for (int i = idx; i < HH; i += stride) g_bias[i] = b_ih[i] + b_hh[i];
}

// ---------------- persistent RNN kernel ----------------
__global__ __launch_bounds__(256, 1) void rnn_kernel(const float* __restrict__ x,
                                                     const float* __restrict__ h0) {
    extern __shared__ char smem_raw[];
    float* s_h = (float*)smem_raw;                       // RT*KSMAX = 24576 B
    float* s_w = (float*)(smem_raw + RT * KSMAX * 4);    // KSMAX*JT = 49152 B
    __shared__ int s_b[RT];

    int cta = blockIdx.x;
    int tid = threadIdx.x;
    int cg  = cta & 3;
    int rem = cta >> 2;            // 0..31
    int j0  = cg * JT;
    int ty  = tid >> 5;            // 0..7 (8 rows each)
    int tx  = tid & 31;
    int cb  = tx * 4;

    int cur_tier = -1;
    int ns_prev  = 8;
    bool pendW   = false;

    for (int t = 0; t <= TT; ++t) {
        int A = (t == 0) ? BB : g_active[t - 1];
        if (A == 0) break;                         // uniform across all CTAs

        int tier, rgsh, ns, ks;
        tier_of(A, tier, rgsh, ns, ks);
        int rgi = rem & ((1 << rgsh) - 1);
        int z   = rem >> rgsh;
        int r0  = rgi * RT;
        bool busy = (r0 < A);
        int ks4 = ks >> 2;
        int pbR = (t & 1) ^ 1, pbW = t & 1;

        // ---- finalize-only pass (t == TT): write hout[TT-1] ----
        if (t == TT) {
            if (tid < RT) s_b[tid] = g_perm[min(r0 + tid, BB - 1)];
            __syncthreads();
            if (busy && cg == 0) {
                int items = RT * ks4;
                for (int i4 = tid; i4 < items; i4 += 256) {
                    int rl = i4 / ks4;
                    int kl = (i4 % ks4) * 4;
                    int r  = r0 + rl;
                    int kg = z * ks + kl;
                    if (r >= A || kg >= HH) continue;
                    const float* pp = &g_part[pbR][0][r][kg];
                    float4 v = __ldcg((const float4*)pp);
                    for (int zp = 1; zp < ns_prev; ++zp) {
                        float4 p = __ldcg((const float4*)(pp + (size_t)zp * BB * HH));
                        v.x += p.x; v.y += p.y; v.z += p.z; v.w += p.w;
                    }
                    v.x = tanhf(v.x); v.y = tanhf(v.y); v.z = tanhf(v.z); v.w = tanhf(v.w);
                    *(float4*)&g_hout[((size_t)s_b[rl] * TT + (TT - 1)) * HH + kg] = v;
                }
            }
            break;
        }

        // ---- W reload on tier change (even for idle CTAs: z changed) ----
        if (tier != cur_tier) {
            cur_tier = tier;
            int nf4 = ks * (JT / 4);                 // float4 count
            for (int p = tid; p < nf4; p += 256) {
                int kk = p >> 5;
                int jj = (p & 31) * 4;
                cpa16(&s_w[kk * JT + jj], &g_W[(size_t)(z * ks + kk) * HH + j0 + jj]);
            }
            CPA_COMMIT();
            pendW = true;
        }

        if (tid < RT) s_b[tid] = g_perm[min(r0 + tid, BB - 1)];
        __syncthreads();   // s_b visible

        // ---- stage s_h: rows [r0, r0+RT) x k-slice; reduce partials + tanh; hout[t-1] ----
        if (busy) {
            int items = RT * ks4;
            for (int i4 = tid; i4 < items; i4 += 256) {
                int rl = i4 / ks4;
                int kl = (i4 % ks4) * 4;
                int r  = r0 + rl;
                int kg = z * ks + kl;
                float4 v;
                if (r >= A) {
                    v.x = v.y = v.z = v.w = 0.f;
                } else if (kg < HH) {
                    if (t == 0) {
                        v = *(const float4*)&h0[(size_t)s_b[rl] * HH + kg];
                    } else {
                        const float* pp = &g_part[pbR][0][r][kg];
                        v = __ldcg((const float4*)pp);
                        for (int zp = 1; zp < ns_prev; ++zp) {
                            float4 p = __ldcg((const float4*)(pp + (size_t)zp * BB * HH));
                            v.x += p.x; v.y += p.y; v.z += p.z; v.w += p.w;
                        }
                        v.x = tanhf(v.x); v.y = tanhf(v.y); v.z = tanhf(v.z); v.w = tanhf(v.w);
                        if (cg == 0)
                            *(float4*)&g_hout[((size_t)s_b[rl] * TT + (t - 1)) * HH + kg] = v;
                    }
                } else {
                    v = *(const float4*)&x[((size_t)s_b[rl] * TT + t) * II + (kg - HH)];
                }
                *(float4*)&s_h[rl * ks + kl] = v;
            }
        }

        if (pendW) { CPA_WAIT0(); pendW = false; }
        __syncthreads();   // s_h + s_w ready

        // ---- GEMM: 8x4 per thread, warps with no active rows skip ----
        int rows_here = min(RT, A - r0);
        if (busy && 8 * ty < rows_here) {
            float acc[8][4];
            #pragma unroll
            for (int i = 0; i < 8; ++i)
                #pragma unroll
                for (int c = 0; c < 4; ++c) acc[i][c] = 0.f;

            const float* shb = s_h + (8 * ty) * ks;
            #pragma unroll 2
            for (int k4 = 0; k4 < ks4; ++k4) {
                float4 wv[4];
                #pragma unroll
                for (int kk = 0; kk < 4; ++kk)
                    wv[kk] = *(const float4*)&s_w[(k4 * 4 + kk) * JT + cb];
                #pragma unroll
                for (int i = 0; i < 8; ++i) {
                    float4 hv = *(const float4*)&shb[i * ks + k4 * 4];
                    acc[i][0] = fmaf(hv.x, wv[0].x, acc[i][0]);
                    acc[i][1] = fmaf(hv.x, wv[0].y, acc[i][1]);
                    acc[i][2] = fmaf(hv.x, wv[0].z, acc[i][2]);
                    acc[i][3] = fmaf(hv.x, wv[0].w, acc[i][3]);
                    acc[i][0] = fmaf(hv.y, wv[1].x, acc[i][0]);
                    acc[i][1] = fmaf(hv.y, wv[1].y, acc[i][1]);
                    acc[i][2] = fmaf(hv.y, wv[1].z, acc[i][2]);
                    acc[i][3] = fmaf(hv.y, wv[1].w, acc[i][3]);
                    acc[i][0] = fmaf(hv.z, wv[2].x, acc[i][0]);
                    acc[i][1] = fmaf(hv.z, wv[2].y, acc[i][1]);
                    acc[i][2] = fmaf(hv.z, wv[2].z, acc[i][2]);
                    acc[i][3] = fmaf(hv.z, wv[2].w, acc[i][3]);
                    acc[i][0] = fmaf(hv.w, wv[3].x, acc[i][0]);
                    acc[i][1] = fmaf(hv.w, wv[3].y, acc[i][1]);
                    acc[i][2] = fmaf(hv.w, wv[3].z, acc[i][2]);
                    acc[i][3] = fmaf(hv.w, wv[3].w, acc[i][3]);
                }
            }

            // epilogue: write partials (bias folded into slice 0)
            int j = j0 + cb;
            float4 bv = make_float4(0.f, 0.f, 0.f, 0.f);
            if (z == 0) bv = *(const float4*)&g_bias[j];
            #pragma unroll
            for (int i = 0; i < 8; ++i) {
                int r = r0 + 8 * ty + i;
                float4 v = make_float4(acc[i][0] + bv.x, acc[i][1] + bv.y,
                                       acc[i][2] + bv.z, acc[i][3] + bv.w);
                __stcg((float4*)&g_part[pbW][z][r][j], v);
            }
        }

        grid_sync(t + 1);
        ns_prev = ns;
    }
}

// ---------------- FC head ----------------
__global__ __launch_bounds__(256) void fc_kernel(const int* __restrict__ lengths,
                                                 const float* __restrict__ W_fc,
                                                 const float* __restrict__ b_fc,
                                                 float* __restrict__ out,
                                                 int write_len_tail) {
    __shared__ float s_w[AA][HH];
    __shared__ float s_bias[AA];
    int tid = threadIdx.x;
    for (int i = tid; i < AA * HH; i += 256) s_w[i / HH][i % HH] = W_fc[i];
    if (tid < AA) s_bias[tid] = b_fc[tid];
    __syncthreads();

    int lane = tid & 31, wid = tid >> 5;
    int gw = blockIdx.x * 8 + wid;
    int nw = gridDim.x * 8;
    float myb = s_bias[lane < AA ? lane : 0];

    for (int item = gw; item < BB * TT; item += nw) {
        int b = item / TT, t = item % TT;
        int len = __ldg(&lengths[b]);
        float res;
        if (t < len) {
            const float4* hp = (const float4*)&g_hout[(size_t)item * HH];
            float4 h[4];
            #pragma unroll
            for (int q = 0; q < 4; ++q) h[q] = hp[q * 32 + lane];
            float myval = 0.f;
            #pragma unroll
            for (int a = 0; a < AA; ++a) {
                const float4* wp = (const float4*)&s_w[a][0];
                float p = 0.f;
                #pragma unroll
                for (int q = 0; q < 4; ++q) {
                    float4 w = wp[q * 32 + lane];
                    p = fmaf(h[q].x, w.x, p); p = fmaf(h[q].y, w.y, p);
                    p = fmaf(h[q].z, w.z, p); p = fmaf(h[q].w, w.w, p);
                }
                p += __shfl_xor_sync(0xFFFFFFFFu, p, 16);
                p += __shfl_xor_sync(0xFFFFFFFFu, p, 8);
                p += __shfl_xor_sync(0xFFFFFFFFu, p, 4);
                p += __shfl_xor_sync(0xFFFFFFFFu, p, 2);
                p += __shfl_xor_sync(0xFFFFFFFFu, p, 1);
                if (lane == a) myval = p;
            }
            res = myval + myb;
        } else {
            res = myb;
        }
        if (lane < AA) out[(size_t)item * AA + lane] = res;
    }

    if (write_len_tail && blockIdx.x == 0 && tid < BB) {
        out[(size_t)BB * TT * AA + tid] = (float)__ldg(&lengths[tid]);
    }
}

// ---------------- launch ----------------
extern "C" void kernel_launch(void* const* d_in, const int* in_sizes, int n_in,
                              void* d_out, int out_size) {
    const float* x      = (const float*)d_in[0];
    const float* h0     = (const float*)d_in[1];
    const int*   lengths= (const int*)  d_in[2];
    const float* W_ih   = (const float*)d_in[3];
    const float* W_hh   = (const float*)d_in[4];
    const float* b_ih   = (const float*)d_in[5];
    const float* b_hh   = (const float*)d_in[6];
    const float* W_fc   = (const float*)d_in[7];
    const float* b_fc   = (const float*)d_in[8];
    float* out = (float*)d_out;

    const int smem_bytes = RT * KSMAX * 4 + KSMAX * JT * 4;   // 24576 + 49152 = 73728
    cudaFuncSetAttribute(rnn_kernel, cudaFuncAttributeMaxDynamicSharedMemorySize, smem_bytes);

    prep_sort<<<1, 512>>>(lengths);
    prep_pack<<<512, 256>>>(W_ih, W_hh, b_ih, b_hh);

    rnn_kernel<<<NCTA, 256, smem_bytes>>>(x, h0);

    int tail = (out_size >= BB * TT * AA + BB) ? 1 : 0;
    fc_kernel<<<512, 256>>>(lengths, W_fc, b_fc, out, tail);
}

// round 5
// speedup vs baseline: 1.0004x; 1.0004x over previous
#include <cuda_runtime.h>
#include <math.h>

#define BB 256
#define TT 512
#define II 256
#define HH 512
#define AA 18
#define KK 768
#define NCTA 128
#define RT 64           // rows per CTA
#define JT 128          // cols per CTA
#define NSMAX 32
#define KSMAX 96

// ---------------- scratch ----------------
__device__ float g_W[(size_t)KK * HH];                         // [k][j]
__device__ float g_bias[HH];
__device__ float g_part[2][NSMAX][BB][HH];                     // 32 MB, parity-double-buffered
__device__ float g_hout[(size_t)BB * TT * HH];
__device__ int   g_perm[BB];
__device__ int   g_active[TT];
__device__ int   g_count;
__device__ int   g_gen;

// ---------------- cp.async ----------------
__device__ __forceinline__ void cpa16(void* sdst, const void* gsrc) {
    unsigned s = (unsigned)__cvta_generic_to_shared(sdst);
    asm volatile("cp.async.cg.shared.global [%0], [%1], 16;\n" :: "r"(s), "l"(gsrc));
}
#define CPA_COMMIT() asm volatile("cp.async.commit_group;\n" ::: "memory")
#define CPA_WAIT0()  asm volatile("cp.async.wait_group 0;\n" ::: "memory")

// ---------------- grid barrier (all 128 CTAs co-resident) ----------------
__device__ __forceinline__ void grid_sync(int target) {
    __syncthreads();
    if (threadIdx.x == 0) {
        __threadfence();
        int a = atomicAdd(&g_count, 1);
        if (a == NCTA * target - 1) {
            atomicExch(&g_gen, target);
        } else {
            while (*((volatile int*)&g_gen) < target) { }
            __threadfence();
        }
    }
    __syncthreads();
}

// ---------------- tiers ----------------
__device__ __forceinline__ void tier_of(int A, int& tier, int& rgsh, int& ns, int& ks) {
    if (A > 128)      { tier = 0; rgsh = 2; ns = 8;  ks = 96; }
    else if (A > 64)  { tier = 1; rgsh = 1; ns = 16; ks = 48; }
    else              { tier = 2; rgsh = 0; ns = 32; ks = 24; }
}

// ---------------- prep ----------------
__global__ void prep_sort(const int* __restrict__ lengths) {
    __shared__ int s_len[BB];
    __shared__ int s_hist[TT + 1];
    __shared__ int s_S[TT + 1];
    __shared__ int s_base[TT + 1];
    int tid = threadIdx.x;
    if (tid == 0) { g_count = 0; g_gen = 0; }
    if (tid < BB) s_len[tid] = lengths[tid];
    for (int i = tid; i <= TT; i += blockDim.x) s_hist[i] = 0;
    __syncthreads();
    if (tid < BB) atomicAdd(&s_hist[s_len[tid]], 1);
    __syncthreads();
    if (tid == 0) {
        s_S[TT] = 0;
        for (int v = TT - 1; v >= 0; --v) s_S[v] = s_S[v + 1] + s_hist[v + 1];
    }
    __syncthreads();
    for (int i = tid; i <= TT; i += blockDim.x) s_base[i] = s_S[i];
    if (tid < TT) g_active[tid] = s_S[tid];
    __syncthreads();
    if (tid < BB) {
        int pos = atomicAdd(&s_base[s_len[tid]], 1);
        g_perm[pos] = tid;
    }
}

__global__ void prep_pack(const float* __restrict__ W_ih, const float* __restrict__ W_hh,
                          const float* __restrict__ b_ih, const float* __restrict__ b_hh) {
    int idx = blockIdx.x * blockDim.x + threadIdx.x;
    int stride = gridDim.x * blockDim.x;
    for (int i = idx; i < KK * HH; i += stride) {
        int k = i / HH, j = i % HH;
        g_W[i] = (k < HH) ? W_hh[(size_t)j * HH + k] : W_ih[(size_t)j * II + (k - HH)];
    }
    for (int i = idx; i < HH; i += stride) g_bias[i] = b_ih[i] + b_hh[i];
}

// ---------------- persistent RNN kernel ----------------
__global__ __launch_bounds__(256, 1) void rnn_kernel(const float* __restrict__ x,
                                                     const float* __restrict__ h0) {
    extern __shared__ char smem_raw[];
    float* s_h = (float*)smem_raw;                       // RT*KSMAX = 24576 B
    float* s_w = (float*)(smem_raw + RT * KSMAX * 4);    // KSMAX*JT = 49152 B
    __shared__ int s_b[RT];

    int cta = blockIdx.x;
    int tid = threadIdx.x;
    int cg  = cta & 3;
    int rem = cta >> 2;            // 0..31
    int j0  = cg * JT;
    int ty  = tid >> 5;            // 0..7 (8 rows each)
    int tx  = tid & 31;
    int cb  = tx * 4;

    int cur_tier = -1;
    int ns_prev  = 8;
    bool pendW   = false;

    for (int t = 0; t <= TT; ++t) {
        int A = (t == 0) ? BB : g_active[t - 1];
        if (A == 0) break;                         // uniform across all CTAs

        int tier, rgsh, ns, ks;
        tier_of(A, tier, rgsh, ns, ks);
        int rgi = rem & ((1 << rgsh) - 1);
        int z   = rem >> rgsh;
        int r0  = rgi * RT;
        bool busy = (r0 < A);
        int ks4 = ks >> 2;
        int pbR = (t & 1) ^ 1, pbW = t & 1;

        // ---- finalize-only pass (t == TT): write hout[TT-1] ----
        if (t == TT) {
            if (tid < RT) s_b[tid] = g_perm[min(r0 + tid, BB - 1)];
            __syncthreads();
            if (busy && cg == 0) {
                int items = RT * ks4;
                for (int i4 = tid; i4 < items; i4 += 256) {
                    int rl = i4 / ks4;
                    int kl = (i4 % ks4) * 4;
                    int r  = r0 + rl;
                    int kg = z * ks + kl;
                    if (r >= A || kg >= HH) continue;
                    const float* pp = &g_part[pbR][0][r][kg];
                    float4 v = __ldcg((const float4*)pp);
                    for (int zp = 1; zp < ns_prev; ++zp) {
                        float4 p = __ldcg((const float4*)(pp + (size_t)zp * BB * HH));
                        v.x += p.x; v.y += p.y; v.z += p.z; v.w += p.w;
                    }
                    v.x = tanhf(v.x); v.y = tanhf(v.y); v.z = tanhf(v.z); v.w = tanhf(v.w);
                    *(float4*)&g_hout[((size_t)s_b[rl] * TT + (TT - 1)) * HH + kg] = v;
                }
            }
            break;
        }

        // ---- W reload on tier change (even for idle CTAs: z changed) ----
        if (tier != cur_tier) {
            cur_tier = tier;
            int nf4 = ks * (JT / 4);                 // float4 count
            for (int p = tid; p < nf4; p += 256) {
                int kk = p >> 5;
                int jj = (p & 31) * 4;
                cpa16(&s_w[kk * JT + jj], &g_W[(size_t)(z * ks + kk) * HH + j0 + jj]);
            }
            CPA_COMMIT();
            pendW = true;
        }

        if (tid < RT) s_b[tid] = g_perm[min(r0 + tid, BB - 1)];
        __syncthreads();   // s_b visible

        // ---- stage s_h: rows [r0, r0+RT) x k-slice; reduce partials + tanh; hout[t-1] ----
        if (busy) {
            int items = RT * ks4;
            for (int i4 = tid; i4 < items; i4 += 256) {
                int rl = i4 / ks4;
                int kl = (i4 % ks4) * 4;
                int r  = r0 + rl;
                int kg = z * ks + kl;
                float4 v;
                if (r >= A) {
                    v.x = v.y = v.z = v.w = 0.f;
                } else if (kg < HH) {
                    if (t == 0) {
                        v = *(const float4*)&h0[(size_t)s_b[rl] * HH + kg];
                    } else {
                        const float* pp = &g_part[pbR][0][r][kg];
                        v = __ldcg((const float4*)pp);
                        for (int zp = 1; zp < ns_prev; ++zp) {
                            float4 p = __ldcg((const float4*)(pp + (size_t)zp * BB * HH));
                            v.x += p.x; v.y += p.y; v.z += p.z; v.w += p.w;
                        }
                        v.x = tanhf(v.x); v.y = tanhf(v.y); v.z = tanhf(v.z); v.w = tanhf(v.w);
                        if (cg == 0)
                            *(float4*)&g_hout[((size_t)s_b[rl] * TT + (t - 1)) * HH + kg] = v;
                    }
                } else {
                    v = *(const float4*)&x[((size_t)s_b[rl] * TT + t) * II + (kg - HH)];
                }
                *(float4*)&s_h[rl * ks + kl] = v;
            }
        }

        if (pendW) { CPA_WAIT0(); pendW = false; }
        __syncthreads();   // s_h + s_w ready

        // ---- GEMM: 8x4 per thread, warps with no active rows skip ----
        int rows_here = min(RT, A - r0);
        if (busy && 8 * ty < rows_here) {
            float acc[8][4];
            #pragma unroll
            for (int i = 0; i < 8; ++i)
                #pragma unroll
                for (int c = 0; c < 4; ++c) acc[i][c] = 0.f;

            const float* shb = s_h + (8 * ty) * ks;
            #pragma unroll 2
            for (int k4 = 0; k4 < ks4; ++k4) {
                float4 wv[4];
                #pragma unroll
                for (int kk = 0; kk < 4; ++kk)
                    wv[kk] = *(const float4*)&s_w[(k4 * 4 + kk) * JT + cb];
                #pragma unroll
                for (int i = 0; i < 8; ++i) {
                    float4 hv = *(const float4*)&shb[i * ks + k4 * 4];
                    acc[i][0] = fmaf(hv.x, wv[0].x, acc[i][0]);
                    acc[i][1] = fmaf(hv.x, wv[0].y, acc[i][1]);
                    acc[i][2] = fmaf(hv.x, wv[0].z, acc[i][2]);
                    acc[i][3] = fmaf(hv.x, wv[0].w, acc[i][3]);
                    acc[i][0] = fmaf(hv.y, wv[1].x, acc[i][0]);
                    acc[i][1] = fmaf(hv.y, wv[1].y, acc[i][1]);
                    acc[i][2] = fmaf(hv.y, wv[1].z, acc[i][2]);
                    acc[i][3] = fmaf(hv.y, wv[1].w, acc[i][3]);
                    acc[i][0] = fmaf(hv.z, wv[2].x, acc[i][0]);
                    acc[i][1] = fmaf(hv.z, wv[2].y, acc[i][1]);
                    acc[i][2] = fmaf(hv.z, wv[2].z, acc[i][2]);
                    acc[i][3] = fmaf(hv.z, wv[2].w, acc[i][3]);
                    acc[i][0] = fmaf(hv.w, wv[3].x, acc[i][0]);
                    acc[i][1] = fmaf(hv.w, wv[3].y, acc[i][1]);
                    acc[i][2] = fmaf(hv.w, wv[3].z, acc[i][2]);
                    acc[i][3] = fmaf(hv.w, wv[3].w, acc[i][3]);
                }
            }

            // epilogue: write partials (bias folded into slice 0)
            int j = j0 + cb;
            float4 bv = make_float4(0.f, 0.f, 0.f, 0.f);
            if (z == 0) bv = *(const float4*)&g_bias[j];
            #pragma unroll
            for (int i = 0; i < 8; ++i) {
                int r = r0 + 8 * ty + i;
                float4 v = make_float4(acc[i][0] + bv.x, acc[i][1] + bv.y,
                                       acc[i][2] + bv.z, acc[i][3] + bv.w);
                __stcg((float4*)&g_part[pbW][z][r][j], v);
            }
        }

        grid_sync(t + 1);
        ns_prev = ns;
    }
}

// ---------------- FC head ----------------
__global__ __launch_bounds__(256) void fc_kernel(const int* __restrict__ lengths,
                                                 const float* __restrict__ W_fc,
                                                 const float* __restrict__ b_fc,
                                                 float* __restrict__ out,
                                                 int write_len_tail) {
    __shared__ float s_w[AA][HH];
    __shared__ float s_bias[AA];
    int tid = threadIdx.x;
    for (int i = tid; i < AA * HH; i += 256) s_w[i / HH][i % HH] = W_fc[i];
    if (tid < AA) s_bias[tid] = b_fc[tid];
    __syncthreads();

    int lane = tid & 31, wid = tid >> 5;
    int gw = blockIdx.x * 8 + wid;
    int nw = gridDim.x * 8;
    float myb = s_bias[lane < AA ? lane : 0];

    for (int item = gw; item < BB * TT; item += nw) {
        int b = item / TT, t = item % TT;
        int len = __ldg(&lengths[b]);
        float res;
        if (t < len) {
            const float4* hp = (const float4*)&g_hout[(size_t)item * HH];
            float4 h[4];
            #pragma unroll
            for (int q = 0; q < 4; ++q) h[q] = hp[q * 32 + lane];
            float myval = 0.f;
            #pragma unroll
            for (int a = 0; a < AA; ++a) {
                const float4* wp = (const float4*)&s_w[a][0];
                float p = 0.f;
                #pragma unroll
                for (int q = 0; q < 4; ++q) {
                    float4 w = wp[q * 32 + lane];
                    p = fmaf(h[q].x, w.x, p); p = fmaf(h[q].y, w.y, p);
                    p = fmaf(h[q].z, w.z, p); p = fmaf(h[q].w, w.w, p);
                }
                p += __shfl_xor_sync(0xFFFFFFFFu, p, 16);
                p += __shfl_xor_sync(0xFFFFFFFFu, p, 8);
                p += __shfl_xor_sync(0xFFFFFFFFu, p, 4);
                p += __shfl_xor_sync(0xFFFFFFFFu, p, 2);
                p += __shfl_xor_sync(0xFFFFFFFFu, p, 1);
                if (lane == a) myval = p;
            }
            res = myval + myb;
        } else {
            res = myb;
        }
        if (lane < AA) out[(size_t)item * AA + lane] = res;
    }

    if (write_len_tail && blockIdx.x == 0 && tid < BB) {
        out[(size_t)BB * TT * AA + tid] = (float)__ldg(&lengths[tid]);
    }
}

// ---------------- launch ----------------
extern "C" void kernel_launch(void* const* d_in, const int* in_sizes, int n_in,
                              void* d_out, int out_size) {
    const float* x      = (const float*)d_in[0];
    const float* h0     = (const float*)d_in[1];
    const int*   lengths= (const int*)  d_in[2];
    const float* W_ih   = (const float*)d_in[3];
    const float* W_hh   = (const float*)d_in[4];
    const float* b_ih   = (const float*)d_in[5];
    const float* b_hh   = (const float*)d_in[6];
    const float* W_fc   = (const float*)d_in[7];
    const float* b_fc   = (const float*)d_in[8];
    float* out = (float*)d_out;

    const int smem_bytes = RT * KSMAX * 4 + KSMAX * JT * 4;   // 24576 + 49152 = 73728
    cudaFuncSetAttribute(rnn_kernel, cudaFuncAttributeMaxDynamicSharedMemorySize, smem_bytes);

    prep_sort<<<1, 512>>>(lengths);
    prep_pack<<<512, 256>>>(W_ih, W_hh, b_ih, b_hh);

    rnn_kernel<<<NCTA, 256, smem_bytes>>>(x, h0);

    int tail = (out_size >= BB * TT * AA + BB) ? 1 : 0;
    fc_kernel<<<512, 256>>>(lengths, W_fc, b_fc, out, tail);
}

// round 11
// speedup vs baseline: 1.4090x; 1.4084x over previous
#include <cuda_runtime.h>
#include <math.h>

#if defined(__CUDA_ARCH_FEAT_SM103_ALL) || defined(__CUDA_ARCH_FEAT_SM100_ALL) || defined(__CUDA_ARCH_SPECIFIC__)
#define F32X2_OK 1
#else
#define F32X2_OK 0
#endif

#define BB 256
#define TT 512
#define II 256
#define HH 512
#define AA 18
#define KK 768
#define NS 8            // k slices
#define KS 96           // k per slice
#define JT 128          // cols per CTA
#define RT 32           // rows per CTA
#define KC 24           // k chunk (double buffered, 4 chunks per slice)

// ---------------- scratch (static device globals; no allocation) ----------------
__device__ float g_W[(size_t)KK * HH];             // [k][j] k<512 -> W_hh[j][k], else W_ih[j][k-512]
__device__ float g_bias[HH];
__device__ float g_part[2][NS][BB][HH];            // per-slice partial pre-activations (parity buffered)
__device__ float g_hout[(size_t)BB * TT * HH];
__device__ int   g_perm[BB];
__device__ int   g_active[TT];

// ---------------- cp.async helpers ----------------
__device__ __forceinline__ void cpa16(void* sdst, const void* gsrc) {
    unsigned s = (unsigned)__cvta_generic_to_shared(sdst);
    asm volatile("cp.async.cg.shared.global [%0], [%1], 16;\n" :: "r"(s), "l"(gsrc));
}
#define CPA_COMMIT() asm volatile("cp.async.commit_group;\n" ::: "memory")
#define CPA_WAIT1()  asm volatile("cp.async.wait_group 1;\n" ::: "memory")
#define CPA_WAIT0()  asm volatile("cp.async.wait_group 0;\n" ::: "memory")

// ---------------- f32x2 packed-FMA helpers (sm_103a pass only) ----------------
#if F32X2_OK
__device__ __forceinline__ void fma2(unsigned long long& d, unsigned long long a, unsigned long long b) {
    asm("fma.rn.f32x2 %0, %1, %2, %0;" : "+l"(d) : "l"(a), "l"(b));
}
__device__ __forceinline__ unsigned long long packdup(float h) {
    unsigned long long r;
    unsigned hb = __float_as_uint(h);
    asm("mov.b64 %0, {%1, %1};" : "=l"(r) : "r"(hb));
    return r;
}
__device__ __forceinline__ void unpack2(unsigned long long v, float& lo, float& hi) {
    unsigned a, b;
    asm("mov.b64 {%0, %1}, %2;" : "=r"(a), "=r"(b) : "l"(v));
    lo = __uint_as_float(a); hi = __uint_as_float(b);
}
#endif

// ---------------- prep: counting sort by length (desc) + active counts ----------------
__global__ void prep_sort(const int* __restrict__ lengths) {
    __shared__ int s_len[BB];
    __shared__ int s_hist[TT + 1];
    __shared__ int s_S[TT + 1];
    __shared__ int s_base[TT + 1];
    int tid = threadIdx.x;          // 512 threads
    if (tid < BB) s_len[tid] = lengths[tid];
    for (int i = tid; i <= TT; i += blockDim.x) s_hist[i] = 0;
    __syncthreads();
    if (tid < BB) atomicAdd(&s_hist[s_len[tid]], 1);
    __syncthreads();
    if (tid == 0) {
        s_S[TT] = 0;
        for (int v = TT - 1; v >= 0; --v) s_S[v] = s_S[v + 1] + s_hist[v + 1];
    }
    __syncthreads();
    for (int i = tid; i <= TT; i += blockDim.x) s_base[i] = s_S[i];
    if (tid < TT) g_active[tid] = s_S[tid];
    __syncthreads();
    if (tid < BB) {
        int pos = atomicAdd(&s_base[s_len[tid]], 1);
        g_perm[pos] = tid;
    }
}

// ---------------- prep: pack W concat k-major, bias ----------------
__global__ void prep_pack(const float* __restrict__ W_ih, const float* __restrict__ W_hh,
                          const float* __restrict__ b_ih, const float* __restrict__ b_hh) {
    int idx = blockIdx.x * blockDim.x + threadIdx.x;
    int stride = gridDim.x * blockDim.x;
    for (int i = idx; i < KK * HH; i += stride) {
        int k = i / HH, j = i % HH;
        g_W[i] = (k < HH) ? W_hh[(size_t)j * HH + k] : W_ih[(size_t)j * II + (k - HH)];
    }
    for (int i = idx; i < HH; i += stride) g_bias[i] = b_ih[i] + b_hh[i];
}

// ---------------- step kernel ----------------
// kernel(t): stage h_{t-1} from partials (tanh, +g_hout[t-1] writeout), GEMM slice -> partials for h_t.
// t == TT: finalize-only pass (writes g_hout[TT-1]).
// grid: (HH/JT=4, BB/RT=8, NS=8) = 256 CTAs, 256 threads, 36KB smem -> 2 CTAs/SM.
__global__ __launch_bounds__(256, 2) void step_kernel(const float* __restrict__ x,
                                                      const float* __restrict__ h0,
                                                      int t) {
    int a_prev = (t == 0) ? BB : g_active[t - 1];
    int r0 = blockIdx.y * RT;
    if (r0 >= a_prev) return;
    int nrows = min(RT, a_prev - r0);
    int z  = blockIdx.z;
    int cg = blockIdx.x;
    int j0 = cg * JT;
    int tid = threadIdx.x;
    int pbR = (t & 1) ^ 1;   // partials written by step t-1
    int pbW = t & 1;

    __shared__ int s_b[RT];
    if (tid < RT) s_b[tid] = g_perm[r0 + tid];

    const int KS4 = KS / 4;   // 24

    // ---- finalize-only pass ----
    if (t == TT) {
        __syncthreads();
        if (cg != 0 || z >= 6) return;
        for (int i4 = tid; i4 < RT * KS4; i4 += 256) {
            int rl = i4 / KS4;
            int kl = (i4 % KS4) * 4;
            int r  = r0 + rl;
            int kg = z * KS + kl;
            if (r >= a_prev || kg >= HH) continue;
            float4 v = *(const float4*)&g_part[pbR][0][r][kg];
            #pragma unroll
            for (int zp = 1; zp < NS; ++zp) {
                float4 p = *(const float4*)&g_part[pbR][zp][r][kg];
                v.x += p.x; v.y += p.y; v.z += p.z; v.w += p.w;
            }
            v.x = tanhf(v.x); v.y = tanhf(v.y); v.z = tanhf(v.z); v.w = tanhf(v.w);
            *(float4*)&g_hout[((size_t)s_b[rl] * TT + (TT - 1)) * HH + kg] = v;
        }
        return;
    }

    extern __shared__ char smem_raw[];
    float (*s_h)[KS]     = (float (*)[KS])smem_raw;                      // 12 KB
    float* s_w           = (float*)(smem_raw + RT * KS * 4);             // 2 x 12 KB

    // issue W chunk 0 and 1 loads (cp.async, overlap with staging)
    #pragma unroll
    for (int c = 0; c < 2; ++c) {
        int kb = z * KS + c * KC;
        const float* gw = g_W + (size_t)kb * HH + j0;
        float* dst = s_w + c * (KC * JT);
        #pragma unroll
        for (int q = 0; q < (KC * JT / 4) / 256; ++q) {   // 3
            int p  = tid + q * 256;
            int kk = p >> 5;
            int jj = (p & 31) * 4;
            cpa16(&dst[kk * JT + jj], gw + (size_t)kk * HH + jj);
        }
        CPA_COMMIT();
    }
    __syncthreads();   // s_b visible

    // ---- stage s_h: h part = tanh(sum of NS partials); x part from gmem ----
    for (int i4 = tid; i4 < RT * KS4; i4 += 256) {
        int rl = i4 / KS4;
        int kl = (i4 % KS4) * 4;
        int r  = r0 + rl;
        int kg = z * KS + kl;
        float4 v;
        if (r >= a_prev) {
            v.x = v.y = v.z = v.w = 0.f;
        } else if (kg < HH) {
            if (t == 0) {
                v = *(const float4*)&h0[(size_t)s_b[rl] * HH + kg];
            } else {
                v = *(const float4*)&g_part[pbR][0][r][kg];
                #pragma unroll
                for (int zp = 1; zp < NS; ++zp) {
                    float4 p = *(const float4*)&g_part[pbR][zp][r][kg];
                    v.x += p.x; v.y += p.y; v.z += p.z; v.w += p.w;
                }
                v.x = tanhf(v.x); v.y = tanhf(v.y); v.z = tanhf(v.z); v.w = tanhf(v.w);
                if (cg == 0)
                    *(float4*)&g_hout[((size_t)s_b[rl] * TT + (t - 1)) * HH + kg] = v;
            }
        } else {
            v = *(const float4*)&x[((size_t)s_b[rl] * TT + t) * II + (kg - HH)];
        }
        *(float4*)&s_h[rl][kl] = v;
    }

    // ---- GEMM: 32x128 tile, 4x4 per thread, 4 chunks of KC=24, double-buffered ----
    int ty = tid >> 5;          // 0..7 (row group of 4)
    int tx = tid & 31;          // 0..31 (col group of 4)
    int cb = tx * 4;

#if F32X2_OK
    unsigned long long acc2[4][2];
    #pragma unroll
    for (int i = 0; i < 4; ++i) { acc2[i][0] = 0ull; acc2[i][1] = 0ull; }
#else
    float acc[4][4];
    #pragma unroll
    for (int i = 0; i < 4; ++i)
        #pragma unroll
        for (int jj = 0; jj < 4; ++jj) acc[i][jj] = 0.f;
#endif

    #pragma unroll
    for (int c = 0; c < 4; ++c) {
        if (c == 3) { CPA_WAIT0(); } else { CPA_WAIT1(); }
        __syncthreads();   // chunk c ready in buffer c&1; s_h ready (first iter)
        const float* wb = s_w + (c & 1) * (KC * JT);
        int koff = c * KC;
        #pragma unroll
        for (int k4 = 0; k4 < KC / 4; ++k4) {
            float4 hv[4];
            #pragma unroll
            for (int i = 0; i < 4; ++i)
                hv[i] = *(const float4*)&s_h[4 * ty + i][koff + k4 * 4];
#if F32X2_OK
            #pragma unroll
            for (int kk = 0; kk < 4; ++kk) {
                const unsigned long long* wp =
                    (const unsigned long long*)&wb[(k4 * 4 + kk) * JT + cb];
                unsigned long long w01 = wp[0];
                unsigned long long w23 = wp[1];
                #pragma unroll
                for (int i = 0; i < 4; ++i) {
                    float hh = (kk == 0) ? hv[i].x : (kk == 1) ? hv[i].y
                             : (kk == 2) ? hv[i].z : hv[i].w;
                    unsigned long long h2 = packdup(hh);
                    fma2(acc2[i][0], h2, w01);
                    fma2(acc2[i][1], h2, w23);
                }
            }
#else
            #pragma unroll
            for (int kk = 0; kk < 4; ++kk) {
                float4 wv = *(const float4*)&wb[(k4 * 4 + kk) * JT + cb];
                #pragma unroll
                for (int i = 0; i < 4; ++i) {
                    float hh = (kk == 0) ? hv[i].x : (kk == 1) ? hv[i].y
                             : (kk == 2) ? hv[i].z : hv[i].w;
                    acc[i][0] = fmaf(hh, wv.x, acc[i][0]);
                    acc[i][1] = fmaf(hh, wv.y, acc[i][1]);
                    acc[i][2] = fmaf(hh, wv.z, acc[i][2]);
                    acc[i][3] = fmaf(hh, wv.w, acc[i][3]);
                }
            }
#endif
        }
        if (c < 2) {   // all threads done reading buffer c: refill with chunk c+2
            __syncthreads();
            int kb = z * KS + (c + 2) * KC;
            const float* gw = g_W + (size_t)kb * HH + j0;
            float* dst = s_w + (c & 1) * (KC * JT);
            #pragma unroll
            for (int q = 0; q < (KC * JT / 4) / 256; ++q) {
                int p  = tid + q * 256;
                int kk = p >> 5;
                int jj = (p & 31) * 4;
                cpa16(&dst[kk * JT + jj], gw + (size_t)kk * HH + jj);
            }
            CPA_COMMIT();
        }
    }

    // ---- epilogue: write slice partials (bias folded into slice 0) ----
    int j = j0 + cb;
    float4 bv = make_float4(0.f, 0.f, 0.f, 0.f);
    if (z == 0) bv = *(const float4*)&g_bias[j];
    #pragma unroll
    for (int i = 0; i < 4; ++i) {
        int r = r0 + 4 * ty + i;
        float4 v;
#if F32X2_OK
        unpack2(acc2[i][0], v.x, v.y);
        unpack2(acc2[i][1], v.z, v.w);
#else
        v = make_float4(acc[i][0], acc[i][1], acc[i][2], acc[i][3]);
#endif
        v.x += bv.x; v.y += bv.y; v.z += bv.z; v.w += bv.w;
        *(float4*)&g_part[pbW][z][r][j] = v;
    }
}

// ---------------- FC head ----------------
__global__ __launch_bounds__(256) void fc_kernel(const int* __restrict__ lengths,
                                                 const float* __restrict__ W_fc,
                                                 const float* __restrict__ b_fc,
                                                 float* __restrict__ out,
                                                 int write_len_tail) {
    __shared__ float s_w[AA][HH];
    __shared__ float s_bias[AA];
    int tid = threadIdx.x;
    for (int i = tid; i < AA * HH; i += 256) s_w[i / HH][i % HH] = W_fc[i];
    if (tid < AA) s_bias[tid] = b_fc[tid];
    __syncthreads();

    int lane = tid & 31, wid = tid >> 5;
    int gw = blockIdx.x * 8 + wid;
    int nw = gridDim.x * 8;
    float myb = s_bias[lane < AA ? lane : 0];

    for (int item = gw; item < BB * TT; item += nw) {
        int b = item / TT, t = item % TT;
        int len = __ldg(&lengths[b]);
        float res;
        if (t < len) {
            const float4* hp = (const float4*)&g_hout[(size_t)item * HH];
            float4 h[4];
            #pragma unroll
            for (int q = 0; q < 4; ++q) h[q] = hp[q * 32 + lane];
            float myval = 0.f;
            #pragma unroll
            for (int a = 0; a < AA; ++a) {
                const float4* wp = (const float4*)&s_w[a][0];
                float p = 0.f;
                #pragma unroll
                for (int q = 0; q < 4; ++q) {
                    float4 w = wp[q * 32 + lane];
                    p = fmaf(h[q].x, w.x, p); p = fmaf(h[q].y, w.y, p);
                    p = fmaf(h[q].z, w.z, p); p = fmaf(h[q].w, w.w, p);
                }
                p += __shfl_xor_sync(0xFFFFFFFFu, p, 16);
                p += __shfl_xor_sync(0xFFFFFFFFu, p, 8);
                p += __shfl_xor_sync(0xFFFFFFFFu, p, 4);
                p += __shfl_xor_sync(0xFFFFFFFFu, p, 2);
                p += __shfl_xor_sync(0xFFFFFFFFu, p, 1);
                if (lane == a) myval = p;
            }
            res = myval + myb;
        } else {
            res = myb;
        }
        if (lane < AA) out[(size_t)item * AA + lane] = res;
    }

    if (write_len_tail && blockIdx.x == 0 && tid < BB) {
        out[(size_t)BB * TT * AA + tid] = (float)__ldg(&lengths[tid]);
    }
}

// ---------------- launch ----------------
extern "C" void kernel_launch(void* const* d_in, const int* in_sizes, int n_in,
                              void* d_out, int out_size) {
    const float* x      = (const float*)d_in[0];
    const float* h0     = (const float*)d_in[1];
    const int*   lengths= (const int*)  d_in[2];
    const float* W_ih   = (const float*)d_in[3];
    const float* W_hh   = (const float*)d_in[4];
    const float* b_ih   = (const float*)d_in[5];
    const float* b_hh   = (const float*)d_in[6];
    const float* W_fc   = (const float*)d_in[7];
    const float* b_fc   = (const float*)d_in[8];
    float* out = (float*)d_out;

    const int smem_bytes = RT * KS * 4 + 2 * KC * JT * 4;   // 12KB + 24KB = 36864
    cudaFuncSetAttribute(step_kernel, cudaFuncAttributeMaxDynamicSharedMemorySize, smem_bytes);

    prep_sort<<<1, 512>>>(lengths);
    prep_pack<<<512, 256>>>(W_ih, W_hh, b_ih, b_hh);

    dim3 grid(HH / JT, BB / RT, NS);   // (4, 8, 8) = 256 CTAs
    for (int t = 0; t <= TT; ++t) {
        step_kernel<<<grid, 256, smem_bytes>>>(x, h0, t);
    }

    int tail = (out_size >= BB * TT * AA + BB) ? 1 : 0;
    fc_kernel<<<512, 256>>>(lengths, W_fc, b_fc, out, tail);
}

// round 13
// speedup vs baseline: 1.4157x; 1.0048x over previous
#include <cuda_runtime.h>
#include <math.h>

#if defined(__CUDA_ARCH_FEAT_SM103_ALL) || defined(__CUDA_ARCH_FEAT_SM100_ALL) || defined(__CUDA_ARCH_SPECIFIC__)
#define F32X2_OK 1
#else
#define F32X2_OK 0
#endif

#define BB 256
#define TT 512
#define II 256
#define HH 512
#define AA 18
#define KK 768
#define NS 8            // k slices
#define KS 96           // k per slice
#define JT 128          // cols per CTA
#define RT 32           // rows per CTA

// ---------------- scratch (static device globals; no allocation) ----------------
__device__ float g_W[(size_t)KK * HH];             // [k][j] k<512 -> W_hh[j][k], else W_ih[j][k-512]
__device__ float g_bias[HH];
__device__ float g_part[2][NS][BB][HH];            // per-slice partial pre-activations (parity buffered)
__device__ float g_hout[(size_t)BB * TT * HH];
__device__ int   g_perm[BB];
__device__ int   g_active[TT];

// ---------------- cp.async ----------------
__device__ __forceinline__ void cpa16(void* sdst, const void* gsrc) {
    unsigned s = (unsigned)__cvta_generic_to_shared(sdst);
    asm volatile("cp.async.cg.shared.global [%0], [%1], 16;\n" :: "r"(s), "l"(gsrc));
}
#define CPA_COMMIT() asm volatile("cp.async.commit_group;\n" ::: "memory")
#define CPA_WAIT0()  asm volatile("cp.async.wait_group 0;\n" ::: "memory")

// ---------------- f32x2 packed FMA (sm_103a pass only) ----------------
#if F32X2_OK
__device__ __forceinline__ void fma2(unsigned long long& d, unsigned long long a, unsigned long long b) {
    asm("fma.rn.f32x2 %0, %1, %2, %0;" : "+l"(d) : "l"(a), "l"(b));
}
__device__ __forceinline__ unsigned long long packdup(float h) {
    unsigned long long r;
    unsigned hb = __float_as_uint(h);
    asm("mov.b64 %0, {%1, %1};" : "=l"(r) : "r"(hb));
    return r;
}
__device__ __forceinline__ void unpack2(unsigned long long v, float& lo, float& hi) {
    unsigned a, b;
    asm("mov.b64 {%0, %1}, %2;" : "=r"(a), "=r"(b) : "l"(v));
    lo = __uint_as_float(a); hi = __uint_as_float(b);
}
#endif

// ---------------- prep: counting sort by length (desc) + active counts ----------------
__global__ void prep_sort(const int* __restrict__ lengths) {
    __shared__ int s_len[BB];
    __shared__ int s_hist[TT + 1];
    __shared__ int s_S[TT + 1];
    __shared__ int s_base[TT + 1];
    int tid = threadIdx.x;          // 512 threads
    if (tid < BB) s_len[tid] = lengths[tid];
    for (int i = tid; i <= TT; i += blockDim.x) s_hist[i] = 0;
    __syncthreads();
    if (tid < BB) atomicAdd(&s_hist[s_len[tid]], 1);
    __syncthreads();
    if (tid == 0) {
        s_S[TT] = 0;
        for (int v = TT - 1; v >= 0; --v) s_S[v] = s_S[v + 1] + s_hist[v + 1];
    }
    __syncthreads();
    for (int i = tid; i <= TT; i += blockDim.x) s_base[i] = s_S[i];
    if (tid < TT) g_active[tid] = s_S[tid];
    __syncthreads();
    if (tid < BB) {
        int pos = atomicAdd(&s_base[s_len[tid]], 1);
        g_perm[pos] = tid;
    }
}

// ---------------- prep: pack W concat k-major, bias ----------------
__global__ void prep_pack(const float* __restrict__ W_ih, const float* __restrict__ W_hh,
                          const float* __restrict__ b_ih, const float* __restrict__ b_hh) {
    int idx = blockIdx.x * blockDim.x + threadIdx.x;
    int stride = gridDim.x * blockDim.x;
    for (int i = idx; i < KK * HH; i += stride) {
        int k = i / HH, j = i % HH;
        g_W[i] = (k < HH) ? W_hh[(size_t)j * HH + k] : W_ih[(size_t)j * II + (k - HH)];
    }
    for (int i = idx; i < HH; i += stride) g_bias[i] = b_ih[i] + b_hh[i];
}

// ---------------- step kernel ----------------
// kernel(t): stage h_{t-1} from partials (tanh, +g_hout[t-1] writeout), GEMM slice -> partials for h_t.
// t == TT: finalize-only pass (writes g_hout[TT-1]).
// grid: (HH/JT=4, BB/RT=8, NS=8) = 256 CTAs, 256 threads, 60KB smem -> 2 CTAs/SM.
__global__ __launch_bounds__(256, 2) void step_kernel(const float* __restrict__ x,
                                                      const float* __restrict__ h0,
                                                      int t) {
    int a_prev = (t == 0) ? BB : g_active[t - 1];
    int r0 = blockIdx.y * RT;
    if (r0 >= a_prev) return;
    int z  = blockIdx.z;
    int cg = blockIdx.x;
    int j0 = cg * JT;
    int tid = threadIdx.x;
    int pbR = (t & 1) ^ 1;   // partials written by step t-1
    int pbW = t & 1;

    __shared__ int s_b[RT];
    if (tid < RT) s_b[tid] = g_perm[r0 + tid];

    const int KS4 = KS / 4;   // 24

    // ---- finalize-only pass ----
    if (t == TT) {
        __syncthreads();
        if (cg != 0 || z >= 6) return;
        for (int i4 = tid; i4 < RT * KS4; i4 += 256) {
            int rl = i4 / KS4;
            int kl = (i4 % KS4) * 4;
            int r  = r0 + rl;
            int kg = z * KS + kl;
            if (r >= a_prev || kg >= HH) continue;
            float4 v = *(const float4*)&g_part[pbR][0][r][kg];
            #pragma unroll
            for (int zp = 1; zp < NS; ++zp) {
                float4 p = *(const float4*)&g_part[pbR][zp][r][kg];
                v.x += p.x; v.y += p.y; v.z += p.z; v.w += p.w;
            }
            v.x = tanhf(v.x); v.y = tanhf(v.y); v.z = tanhf(v.z); v.w = tanhf(v.w);
            *(float4*)&g_hout[((size_t)s_b[rl] * TT + (TT - 1)) * HH + kg] = v;
        }
        return;
    }

    extern __shared__ char smem_raw[];
    float (*s_h)[KS] = (float (*)[KS])smem_raw;                  // 32 x 96 = 12 KB
    float (*s_w)[JT] = (float (*)[JT])(smem_raw + RT * KS * 4);  // 96 x 128 = 48 KB

    // issue the WHOLE W slice via cp.async (3072 float4, 12/thread), overlapped with staging
    {
        const float* gw = g_W + (size_t)(z * KS) * HH + j0;
        #pragma unroll
        for (int q = 0; q < (KS * JT / 4) / 256; ++q) {   // 12
            int p  = tid + q * 256;
            int kk = p >> 5;
            int jj = (p & 31) * 4;
            cpa16(&s_w[kk][jj], gw + (size_t)kk * HH + jj);
        }
        CPA_COMMIT();
    }
    __syncthreads();   // s_b visible

    // ---- stage s_h: h part = tanh(sum of NS partials); x part from gmem ----
    for (int i4 = tid; i4 < RT * KS4; i4 += 256) {
        int rl = i4 / KS4;
        int kl = (i4 % KS4) * 4;
        int r  = r0 + rl;
        int kg = z * KS + kl;
        float4 v;
        if (r >= a_prev) {
            v.x = v.y = v.z = v.w = 0.f;
        } else if (kg < HH) {
            if (t == 0) {
                v = *(const float4*)&h0[(size_t)s_b[rl] * HH + kg];
            } else {
                v = *(const float4*)&g_part[pbR][0][r][kg];
                #pragma unroll
                for (int zp = 1; zp < NS; ++zp) {
                    float4 p = *(const float4*)&g_part[pbR][zp][r][kg];
                    v.x += p.x; v.y += p.y; v.z += p.z; v.w += p.w;
                }
                v.x = tanhf(v.x); v.y = tanhf(v.y); v.z = tanhf(v.z); v.w = tanhf(v.w);
                if (cg == 0)
                    *(float4*)&g_hout[((size_t)s_b[rl] * TT + (t - 1)) * HH + kg] = v;
            }
        } else {
            v = *(const float4*)&x[((size_t)s_b[rl] * TT + t) * II + (kg - HH)];
        }
        *(float4*)&s_h[rl][kl] = v;
    }

    CPA_WAIT0();
    __syncthreads();   // s_h + s_w ready — single barrier for the whole step

    // ---- GEMM: 32x128 tile, 4 rows x 4 cols per thread, full K=96 uninterrupted ----
    int ty = tid >> 5;          // 0..7 (row group of 4)
    int tx = tid & 31;          // 0..31 (col group of 4)
    int cb = tx * 4;

#if F32X2_OK
    unsigned long long acc2[4][2];
    #pragma unroll
    for (int i = 0; i < 4; ++i) { acc2[i][0] = 0ull; acc2[i][1] = 0ull; }
#else
    float acc[4][4];
    #pragma unroll
    for (int i = 0; i < 4; ++i)
        #pragma unroll
        for (int jj = 0; jj < 4; ++jj) acc[i][jj] = 0.f;
#endif

    #pragma unroll 6
    for (int k4 = 0; k4 < KS4; ++k4) {
        float4 hv[4];
        #pragma unroll
        for (int i = 0; i < 4; ++i)
            hv[i] = *(const float4*)&s_h[4 * ty + i][k4 * 4];
        #pragma unroll
        for (int kk = 0; kk < 4; ++kk) {
#if F32X2_OK
            const unsigned long long* wp =
                (const unsigned long long*)&s_w[k4 * 4 + kk][cb];
            unsigned long long w01 = wp[0];
            unsigned long long w23 = wp[1];
            #pragma unroll
            for (int i = 0; i < 4; ++i) {
                float hh = (kk == 0) ? hv[i].x : (kk == 1) ? hv[i].y
                         : (kk == 2) ? hv[i].z : hv[i].w;
                unsigned long long h2 = packdup(hh);
                fma2(acc2[i][0], h2, w01);
                fma2(acc2[i][1], h2, w23);
            }
#else
            float4 wv = *(const float4*)&s_w[k4 * 4 + kk][cb];
            #pragma unroll
            for (int i = 0; i < 4; ++i) {
                float hh = (kk == 0) ? hv[i].x : (kk == 1) ? hv[i].y
                         : (kk == 2) ? hv[i].z : hv[i].w;
                acc[i][0] = fmaf(hh, wv.x, acc[i][0]);
                acc[i][1] = fmaf(hh, wv.y, acc[i][1]);
                acc[i][2] = fmaf(hh, wv.z, acc[i][2]);
                acc[i][3] = fmaf(hh, wv.w, acc[i][3]);
            }
#endif
        }
    }

    // ---- epilogue: write slice partials (bias folded into slice 0) ----
    int j = j0 + cb;
    float4 bv = make_float4(0.f, 0.f, 0.f, 0.f);
    if (z == 0) bv = *(const float4*)&g_bias[j];
    #pragma unroll
    for (int i = 0; i < 4; ++i) {
        int r = r0 + 4 * ty + i;
        float4 v;
#if F32X2_OK
        unpack2(acc2[i][0], v.x, v.y);
        unpack2(acc2[i][1], v.z, v.w);
#else
        v = make_float4(acc[i][0], acc[i][1], acc[i][2], acc[i][3]);
#endif
        v.x += bv.x; v.y += bv.y; v.z += bv.z; v.w += bv.w;
        *(float4*)&g_part[pbW][z][r][j] = v;
    }
}

// ---------------- FC head ----------------
__global__ __launch_bounds__(256) void fc_kernel(const int* __restrict__ lengths,
                                                 const float* __restrict__ W_fc,
                                                 const float* __restrict__ b_fc,
                                                 float* __restrict__ out,
                                                 int write_len_tail) {
    __shared__ float s_w[AA][HH];
    __shared__ float s_bias[AA];
    int tid = threadIdx.x;
    for (int i = tid; i < AA * HH; i += 256) s_w[i / HH][i % HH] = W_fc[i];
    if (tid < AA) s_bias[tid] = b_fc[tid];
    __syncthreads();

    int lane = tid & 31, wid = tid >> 5;
    int gw = blockIdx.x * 8 + wid;
    int nw = gridDim.x * 8;
    float myb = s_bias[lane < AA ? lane : 0];

    for (int item = gw; item < BB * TT; item += nw) {
        int b = item / TT, t = item % TT;
        int len = __ldg(&lengths[b]);
        float res;
        if (t < len) {
            const float4* hp = (const float4*)&g_hout[(size_t)item * HH];
            float4 h[4];
            #pragma unroll
            for (int q = 0; q < 4; ++q) h[q] = hp[q * 32 + lane];
            float myval = 0.f;
            #pragma unroll
            for (int a = 0; a < AA; ++a) {
                const float4* wp = (const float4*)&s_w[a][0];
                float p = 0.f;
                #pragma unroll
                for (int q = 0; q < 4; ++q) {
                    float4 w = wp[q * 32 + lane];
                    p = fmaf(h[q].x, w.x, p); p = fmaf(h[q].y, w.y, p);
                    p = fmaf(h[q].z, w.z, p); p = fmaf(h[q].w, w.w, p);
                }
                p += __shfl_xor_sync(0xFFFFFFFFu, p, 16);
                p += __shfl_xor_sync(0xFFFFFFFFu, p, 8);
                p += __shfl_xor_sync(0xFFFFFFFFu, p, 4);
                p += __shfl_xor_sync(0xFFFFFFFFu, p, 2);
                p += __shfl_xor_sync(0xFFFFFFFFu, p, 1);
                if (lane == a) myval = p;
            }
            res = myval + myb;
        } else {
            res = myb;
        }
        if (lane < AA) out[(size_t)item * AA + lane] = res;
    }

    if (write_len_tail && blockIdx.x == 0 && tid < BB) {
        out[(size_t)BB * TT * AA + tid] = (float)__ldg(&lengths[tid]);
    }
}

// ---------------- launch ----------------
extern "C" void kernel_launch(void* const* d_in, const int* in_sizes, int n_in,
                              void* d_out, int out_size) {
    const float* x      = (const float*)d_in[0];
    const float* h0     = (const float*)d_in[1];
    const int*   lengths= (const int*)  d_in[2];
    const float* W_ih   = (const float*)d_in[3];
    const float* W_hh   = (const float*)d_in[4];
    const float* b_ih   = (const float*)d_in[5];
    const float* b_hh   = (const float*)d_in[6];
    const float* W_fc   = (const float*)d_in[7];
    const float* b_fc   = (const float*)d_in[8];
    float* out = (float*)d_out;

    const int smem_bytes = RT * KS * 4 + KS * JT * 4;   // 12KB + 48KB = 61440
    cudaFuncSetAttribute(step_kernel, cudaFuncAttributeMaxDynamicSharedMemorySize, smem_bytes);

    prep_sort<<<1, 512>>>(lengths);
    prep_pack<<<512, 256>>>(W_ih, W_hh, b_ih, b_hh);

    dim3 grid(HH / JT, BB / RT, NS);   // (4, 8, 8) = 256 CTAs
    for (int t = 0; t <= TT; ++t) {
        step_kernel<<<grid, 256, smem_bytes>>>(x, h0, t);
    }

    int tail = (out_size >= BB * TT * AA + BB) ? 1 : 0;
    fc_kernel<<<512, 256>>>(lengths, W_fc, b_fc, out, tail);
}